// round 3
// baseline (speedup 1.0000x reference)
#include <cuda_runtime.h>

typedef unsigned long long u64;

__device__ __forceinline__ u64 pack2(float lo, float hi) {
    u64 r;
    asm("mov.b64 %0, {%1, %2};" : "=l"(r) : "r"(__float_as_uint(lo)), "r"(__float_as_uint(hi)));
    return r;
}
__device__ __forceinline__ void unpack2(u64 v, float& lo, float& hi) {
    unsigned int a, b;
    asm("mov.b64 {%0, %1}, %2;" : "=r"(a), "=r"(b) : "l"(v));
    lo = __uint_as_float(a);
    hi = __uint_as_float(b);
}
// Packed fp32x2 FMA/ADD (Blackwell FFMA2).
__device__ __forceinline__ u64 ffma2(u64 a, u64 b, u64 c) {
    u64 d;
    asm("fma.rn.f32x2 %0, %1, %2, %3;" : "=l"(d) : "l"(a), "l"(b), "l"(c));
    return d;
}
__device__ __forceinline__ u64 add2(u64 a, u64 b) {
    u64 d;
    asm("add.rn.f32x2 %0, %1, %2;" : "=l"(d) : "l"(a), "l"(b));
    return d;
}
__device__ __forceinline__ float tanh_fast(float x) {
    float y;
    asm("tanh.approx.f32 %0, %1;" : "=f"(y) : "f"(x));
    return y;
}
// 64-bit shuffle via two 32-bit SHFL.IDX.
__device__ __forceinline__ u64 shfl64(u64 v, int src) {
    unsigned int a, b;
    asm("mov.b64 {%0, %1}, %2;" : "=r"(a), "=r"(b) : "l"(v));
    a = __shfl_sync(0xffffffffu, a, src);
    b = __shfl_sync(0xffffffffu, b, src);
    u64 r;
    asm("mov.b64 %0, {%1, %2};" : "=l"(r) : "r"(a), "r"(b));
    return r;
}

// Systolic 4-layer tanh RNN, 8 threads per batch element.
// Thread = (batch, layer, half): computes 4 of 8 hidden units of its layer.
// Layer l at iteration i computes timestep t = i - l, consuming layer (l-1)'s
// previous-iteration output via lane shuffles. Hidden state is kept as f32x2
// pairs; accumulation runs along packed input pairs (acc[j] holds two partial
// sums, horizontally combined), so every FFMA2 multiplier is a natural
// register pair (no broadcast packs) and each chain is only 4 deep.
//
// ONE_STEP: HEADG = guard h update for t<0; PFG = guard x prefetch vs T.
#define ONE_STEP(IVAL, U, HEADG, PFG)                                           \
    do {                                                                        \
        const int i_ = (IVAL);                                                  \
        /* gather prev-layer output pairs + partner's own-layer pairs */        \
        u64 in0 = shfl64(hp0, prev0);                                           \
        u64 in1 = shfl64(hp1, prev0);                                           \
        u64 in2 = shfl64(hp0, prev1);                                           \
        u64 in3 = shfl64(hp1, prev1);                                           \
        u64 ho0 = shfl64(hp0, partner);                                         \
        u64 ho1 = shfl64(hp1, partner);                                         \
        u64 acc_h0 = biasp[0], acc_h1 = biasp[1], acc_h2 = biasp[2], acc_h3 = biasp[3]; \
        /* hidden-matvec: multipliers [own0, own1, other0, other1]; weight    */\
        /* columns were permuted per-half at load so this order is uniform.   */\
        acc_h0 = ffma2(hp0, whT[0][0], acc_h0);                                 \
        acc_h1 = ffma2(hp0, whT[1][0], acc_h1);                                 \
        acc_h2 = ffma2(hp0, whT[2][0], acc_h2);                                 \
        acc_h3 = ffma2(hp0, whT[3][0], acc_h3);                                 \
        acc_h0 = ffma2(hp1, whT[0][1], acc_h0);                                 \
        acc_h1 = ffma2(hp1, whT[1][1], acc_h1);                                 \
        acc_h2 = ffma2(hp1, whT[2][1], acc_h2);                                 \
        acc_h3 = ffma2(hp1, whT[3][1], acc_h3);                                 \
        acc_h0 = ffma2(ho0, whT[0][2], acc_h0);                                 \
        acc_h1 = ffma2(ho0, whT[1][2], acc_h1);                                 \
        acc_h2 = ffma2(ho0, whT[2][2], acc_h2);                                 \
        acc_h3 = ffma2(ho0, whT[3][2], acc_h3);                                 \
        acc_h0 = ffma2(ho1, whT[0][3], acc_h0);                                 \
        acc_h1 = ffma2(ho1, whT[1][3], acc_h1);                                 \
        acc_h2 = ffma2(ho1, whT[2][3], acc_h2);                                 \
        acc_h3 = ffma2(ho1, whT[3][3], acc_h3);                                 \
        /* input-matvec. Layer 0: substitute (x,x) for pair 0 — its weight    */\
        /* pair is (W_ih0[j], 0) so the hi half contributes 0; pairs 1..3     */\
        /* have zero weights, so garbage 'in' from the wrapped lane is inert. */\
        const u64 d0 = l0 ? pack2(xr[U], xr[U]) : in0;                          \
        u64 acc_i0 = ffma2(d0, wiT[0][0], zero64);                              \
        u64 acc_i1 = ffma2(d0, wiT[1][0], zero64);                              \
        u64 acc_i2 = ffma2(d0, wiT[2][0], zero64);                              \
        u64 acc_i3 = ffma2(d0, wiT[3][0], zero64);                              \
        acc_i0 = ffma2(in1, wiT[0][1], acc_i0);                                 \
        acc_i1 = ffma2(in1, wiT[1][1], acc_i1);                                 \
        acc_i2 = ffma2(in1, wiT[2][1], acc_i2);                                 \
        acc_i3 = ffma2(in1, wiT[3][1], acc_i3);                                 \
        acc_i0 = ffma2(in2, wiT[0][2], acc_i0);                                 \
        acc_i1 = ffma2(in2, wiT[1][2], acc_i1);                                 \
        acc_i2 = ffma2(in2, wiT[2][2], acc_i2);                                 \
        acc_i3 = ffma2(in2, wiT[3][2], acc_i3);                                 \
        acc_i0 = ffma2(in3, wiT[0][3], acc_i0);                                 \
        acc_i1 = ffma2(in3, wiT[1][3], acc_i1);                                 \
        acc_i2 = ffma2(in3, wiT[2][3], acc_i2);                                 \
        acc_i3 = ffma2(in3, wiT[3][3], acc_i3);                                 \
        /* horizontal combine + activation */                                   \
        float l0_, h0_, l1_, h1_, l2_, h2_, l3_, h3_;                           \
        unpack2(add2(acc_i0, acc_h0), l0_, h0_);                                \
        unpack2(add2(acc_i1, acc_h1), l1_, h1_);                                \
        unpack2(add2(acc_i2, acc_h2), l2_, h2_);                                \
        unpack2(add2(acc_i3, acc_h3), l3_, h3_);                                \
        const float n0 = tanh_fast(l0_ + h0_);                                  \
        const float n1 = tanh_fast(l1_ + h1_);                                  \
        const float n2 = tanh_fast(l2_ + h2_);                                  \
        const float n3 = tanh_fast(l3_ + h3_);                                  \
        if (HEADG) {                                                            \
            if ((i_ - layer) >= 0) {                                            \
                hp0 = pack2(n0, n1);                                            \
                hp1 = pack2(n2, n3);                                            \
            }                                                                   \
        } else {                                                                \
            hp0 = pack2(n0, n1);                                                \
            hp1 = pack2(n2, n3);                                                \
        }                                                                       \
        if (PFG) xr[U] = (l0 && (i_ + 4) < T) ? __ldg(xp) : 0.0f;               \
        else     xr[U] = l0 ? __ldg(xp) : 0.0f;                                 \
        xp += B;                                                                \
    } while (0)

__global__ void __launch_bounds__(128, 2) rnn8_kernel(
    const float* __restrict__ x,        // [T, B]
    const float* __restrict__ h0,       // [4, B, 8]
    const float* __restrict__ W_ih0,    // [8, 1]
    const float* __restrict__ W_ih_rest,// [3, 8, 8]
    const float* __restrict__ W_hh,     // [4, 8, 8]
    const float* __restrict__ b_ih,     // [4, 8]
    const float* __restrict__ b_hh,     // [4, 8]
    const float* __restrict__ W_out,    // [1, 8]
    const float* __restrict__ b_out,    // [1]
    float* __restrict__ out,            // [B]
    int T, int B)
{
    const int g     = blockIdx.x * blockDim.x + threadIdx.x;
    const int s     = g & 7;
    const int layer = s >> 1;
    const int half  = s & 1;
    const int b     = g >> 3;
    const int lane  = threadIdx.x & 31;
    const bool l0   = (layer == 0);

    // Shuffle source lanes (within the warp's 8-lane batch group).
    const int grpbase = lane & ~7;
    const int prev0   = grpbase | ((((layer + 3) & 3) << 1) + 0);
    const int prev1   = prev0 + 1;
    const int partner = lane ^ 1;

    // Weights transposed to k-pair form.
    //   wiT[j][m]: input-weight pair for own output j, multiplier slot m = in[m]
    //              (natural k-pair order for all threads).
    //   whT[j][m]: hidden-weight pair; multiplier slots are [own0,own1,oth0,oth1],
    //              so half==1 loads its k-pairs permuted by m^2.
    u64 wiT[4][4], whT[4][4], biasp[4];
    #pragma unroll
    for (int j = 0; j < 4; ++j) {
        const int ju = half * 4 + j;   // global output unit
        biasp[j] = pack2(b_ih[layer * 8 + ju] + b_hh[layer * 8 + ju], 0.0f);
        #pragma unroll
        for (int m = 0; m < 4; ++m) {
            float w0, w1;
            if (l0) {
                w0 = (m == 0) ? W_ih0[ju] : 0.0f;
                w1 = 0.0f;
            } else {
                w0 = W_ih_rest[((layer - 1) * 8 + ju) * 8 + 2 * m];
                w1 = W_ih_rest[((layer - 1) * 8 + ju) * 8 + 2 * m + 1];
            }
            wiT[j][m] = pack2(w0, w1);
            const int kp = half ? (m ^ 2) : m;   // per-half column permutation
            whT[j][m] = pack2(W_hh[(layer * 8 + ju) * 8 + 2 * kp],
                              W_hh[(layer * 8 + ju) * 8 + 2 * kp + 1]);
        }
    }
    const u64 zero64 = pack2(0.0f, 0.0f);

    // Own hidden state: units [half*4 .. half*4+3] as two f32x2 pairs.
    u64 hp0, hp1;
    {
        const float* hsrc = h0 + ((size_t)(layer * B + b)) * 8 + half * 4;
        hp0 = pack2(hsrc[0], hsrc[1]);
        hp1 = pack2(hsrc[2], hsrc[3]);
    }

    const int NITER = T + 3;           // layer 3 finishes t=T-1 at i=T+2

    // 4-deep x prefetch ring (layer-0 threads only).
    float xr[4];
    #pragma unroll
    for (int p = 0; p < 4; ++p)
        xr[p] = (l0 && p < T) ? x[p * B + b] : 0.0f;
    const float* xp = x + (size_t)4 * B + b;

    // Phase 1: head, 4 guarded iterations (t<0 lanes keep h0).
    #pragma unroll
    for (int u = 0; u < 4; ++u)
        ONE_STEP(u, u, true, true);

    // Phase 2: main loop, no guards (prefetch index i+4 <= T-1 guaranteed).
    const int main_end = (T - 4) & ~3;
    for (int io = 4; io < main_end; io += 4) {
        ONE_STEP(io + 0, 0, false, false);
        ONE_STEP(io + 1, 1, false, false);
        ONE_STEP(io + 2, 2, false, false);
        ONE_STEP(io + 3, 3, false, false);
    }

    // Phase 3: epilogue, guarded prefetch only. Post-T updates of layers 0-2
    // are unused and finite; layer 3's last update is exactly t=T-1.
    for (int i = main_end; i < NITER; ++i)
        ONE_STEP(i, i & 3, false, true);

    // Readout: each layer-3 thread has 4 units; combine halves via shuffle.
    float p0, p1, p2, p3;
    unpack2(hp0, p0, p1);
    unpack2(hp1, p2, p3);
    float part = p0 * W_out[half * 4 + 0] + p1 * W_out[half * 4 + 1]
               + p2 * W_out[half * 4 + 2] + p3 * W_out[half * 4 + 3];
    const float other = __shfl_sync(0xffffffffu, part, partner);
    if (layer == 3 && half == 0)
        out[b] = part + other + b_out[0];
}

extern "C" void kernel_launch(void* const* d_in, const int* in_sizes, int n_in,
                              void* d_out, int out_size) {
    const float* x         = (const float*)d_in[0];
    const float* h0        = (const float*)d_in[1];
    const float* W_ih0     = (const float*)d_in[2];
    const float* W_ih_rest = (const float*)d_in[3];
    const float* W_hh      = (const float*)d_in[4];
    const float* b_ih      = (const float*)d_in[5];
    const float* b_hh      = (const float*)d_in[6];
    const float* W_out     = (const float*)d_in[7];
    const float* b_out     = (const float*)d_in[8];

    const int B = in_sizes[1] / 32;   // h0: [4, B, 8]
    const int T = in_sizes[0] / B;    // x:  [T, B, 1]

    const int threads = 8 * B;        // 8 threads per batch element
    const int block   = 128;
    const int grid    = (threads + block - 1) / block;

    rnn8_kernel<<<grid, block>>>(x, h0, W_ih0, W_ih_rest, W_hh, b_ih, b_hh,
                                 W_out, b_out, (float*)d_out, T, B);
}

// round 4
// speedup vs baseline: 1.0376x; 1.0376x over previous
#include <cuda_runtime.h>

typedef unsigned long long u64;

__device__ __forceinline__ u64 pack2(float lo, float hi) {
    u64 r;
    asm("mov.b64 %0, {%1, %2};" : "=l"(r) : "r"(__float_as_uint(lo)), "r"(__float_as_uint(hi)));
    return r;
}
__device__ __forceinline__ void unpack2(u64 v, float& lo, float& hi) {
    unsigned int a, b;
    asm("mov.b64 {%0, %1}, %2;" : "=r"(a), "=r"(b) : "l"(v));
    lo = __uint_as_float(a);
    hi = __uint_as_float(b);
}
// Packed fp32x2 FMA/ADD (Blackwell FFMA2).
__device__ __forceinline__ u64 ffma2(u64 a, u64 b, u64 c) {
    u64 d;
    asm("fma.rn.f32x2 %0, %1, %2, %3;" : "=l"(d) : "l"(a), "l"(b), "l"(c));
    return d;
}
__device__ __forceinline__ u64 add2(u64 a, u64 b) {
    u64 d;
    asm("add.rn.f32x2 %0, %1, %2;" : "=l"(d) : "l"(a), "l"(b));
    return d;
}
__device__ __forceinline__ float tanh_fast(float x) {
    float y;
    asm("tanh.approx.f32 %0, %1;" : "=f"(y) : "f"(x));
    return y;
}

// Systolic 4-layer tanh RNN, 8 threads per batch element, SMEM exchange.
// Thread = (batch, layer, half): computes 4 of 8 hidden units of its layer.
// Layer l at iteration i computes timestep t = i - l. Inter-thread traffic
// (prev-layer h + partner-half h) goes through double-buffered per-warp
// shared memory as 16B ulonglong2 slots: 1 STS.128 + 3 LDS.128 + 1 syncwarp
// per iteration instead of 12 SHFLs. Loaded values arrive pre-packed as
// f32x2 pairs, feeding FFMA2 directly (k-pair accumulation, 4-deep chains).
//
// ONE_STEP: HEADG = guard h update for t<0; PFG = guard x prefetch vs T.
// RD/WR = read/write smem buffers (double-buffered, swapped per iteration).
#define ONE_STEP(IVAL, U, HEADG, PFG, RD, WR)                                   \
    do {                                                                        \
        const int i_ = (IVAL);                                                  \
        const ulonglong2 pv0 = (RD)[prev0];                                     \
        const ulonglong2 pv1 = (RD)[prev1];                                     \
        const ulonglong2 po  = (RD)[partner];                                   \
        const u64 in1 = pv0.y, in2 = pv1.x, in3 = pv1.y;                        \
        const u64 ho0 = po.x,  ho1 = po.y;                                      \
        u64 acc_h0 = biasp[0], acc_h1 = biasp[1], acc_h2 = biasp[2], acc_h3 = biasp[3]; \
        /* hidden-matvec: multipliers [own0, own1, other0, other1]; weight    */\
        /* columns permuted per-half at load so this order is uniform.        */\
        acc_h0 = ffma2(hp0, whT[0][0], acc_h0);                                 \
        acc_h1 = ffma2(hp0, whT[1][0], acc_h1);                                 \
        acc_h2 = ffma2(hp0, whT[2][0], acc_h2);                                 \
        acc_h3 = ffma2(hp0, whT[3][0], acc_h3);                                 \
        acc_h0 = ffma2(hp1, whT[0][1], acc_h0);                                 \
        acc_h1 = ffma2(hp1, whT[1][1], acc_h1);                                 \
        acc_h2 = ffma2(hp1, whT[2][1], acc_h2);                                 \
        acc_h3 = ffma2(hp1, whT[3][1], acc_h3);                                 \
        acc_h0 = ffma2(ho0, whT[0][2], acc_h0);                                 \
        acc_h1 = ffma2(ho0, whT[1][2], acc_h1);                                 \
        acc_h2 = ffma2(ho0, whT[2][2], acc_h2);                                 \
        acc_h3 = ffma2(ho0, whT[3][2], acc_h3);                                 \
        acc_h0 = ffma2(ho1, whT[0][3], acc_h0);                                 \
        acc_h1 = ffma2(ho1, whT[1][3], acc_h1);                                 \
        acc_h2 = ffma2(ho1, whT[2][3], acc_h2);                                 \
        acc_h3 = ffma2(ho1, whT[3][3], acc_h3);                                 \
        /* input-matvec. Layer 0: substitute (x,x) for pair 0 — its weight    */\
        /* pair is (W_ih0[j], 0) so the hi half contributes 0; pairs 1..3     */\
        /* have zero weights, so garbage 'in' from the wrapped slot is inert. */\
        const u64 d0 = l0 ? pack2(xr[U], xr[U]) : pv0.x;                        \
        u64 acc_i0 = ffma2(d0, wiT[0][0], zero64);                              \
        u64 acc_i1 = ffma2(d0, wiT[1][0], zero64);                              \
        u64 acc_i2 = ffma2(d0, wiT[2][0], zero64);                              \
        u64 acc_i3 = ffma2(d0, wiT[3][0], zero64);                              \
        acc_i0 = ffma2(in1, wiT[0][1], acc_i0);                                 \
        acc_i1 = ffma2(in1, wiT[1][1], acc_i1);                                 \
        acc_i2 = ffma2(in1, wiT[2][1], acc_i2);                                 \
        acc_i3 = ffma2(in1, wiT[3][1], acc_i3);                                 \
        acc_i0 = ffma2(in2, wiT[0][2], acc_i0);                                 \
        acc_i1 = ffma2(in2, wiT[1][2], acc_i1);                                 \
        acc_i2 = ffma2(in2, wiT[2][2], acc_i2);                                 \
        acc_i3 = ffma2(in2, wiT[3][2], acc_i3);                                 \
        acc_i0 = ffma2(in3, wiT[0][3], acc_i0);                                 \
        acc_i1 = ffma2(in3, wiT[1][3], acc_i1);                                 \
        acc_i2 = ffma2(in3, wiT[2][3], acc_i2);                                 \
        acc_i3 = ffma2(in3, wiT[3][3], acc_i3);                                 \
        /* horizontal combine + activation */                                   \
        float l0_, h0_, l1_, h1_, l2_, h2_, l3_, h3_;                           \
        unpack2(add2(acc_i0, acc_h0), l0_, h0_);                                \
        unpack2(add2(acc_i1, acc_h1), l1_, h1_);                                \
        unpack2(add2(acc_i2, acc_h2), l2_, h2_);                                \
        unpack2(add2(acc_i3, acc_h3), l3_, h3_);                                \
        const float n0 = tanh_fast(l0_ + h0_);                                  \
        const float n1 = tanh_fast(l1_ + h1_);                                  \
        const float n2 = tanh_fast(l2_ + h2_);                                  \
        const float n3 = tanh_fast(l3_ + h3_);                                  \
        if (HEADG) {                                                            \
            if ((i_ - layer) >= 0) {                                            \
                hp0 = pack2(n0, n1);                                            \
                hp1 = pack2(n2, n3);                                            \
            }                                                                   \
        } else {                                                                \
            hp0 = pack2(n0, n1);                                                \
            hp1 = pack2(n2, n3);                                                \
        }                                                                       \
        (WR)[lane] = make_ulonglong2(hp0, hp1);                                 \
        __syncwarp();                                                           \
        if (PFG) xr[U] = (l0 && (i_ + 4) < T) ? __ldg(xp) : 0.0f;               \
        else     xr[U] = l0 ? __ldg(xp) : 0.0f;                                 \
        xp += B;                                                                \
    } while (0)

__global__ void __launch_bounds__(256, 1) rnn8s_kernel(
    const float* __restrict__ x,        // [T, B]
    const float* __restrict__ h0,       // [4, B, 8]
    const float* __restrict__ W_ih0,    // [8, 1]
    const float* __restrict__ W_ih_rest,// [3, 8, 8]
    const float* __restrict__ W_hh,     // [4, 8, 8]
    const float* __restrict__ b_ih,     // [4, 8]
    const float* __restrict__ b_hh,     // [4, 8]
    const float* __restrict__ W_out,    // [1, 8]
    const float* __restrict__ b_out,    // [1]
    float* __restrict__ out,            // [B]
    int T, int B)
{
    // Double-buffered per-warp exchange: [buf][warp][lane] 16B slots = 8KB.
    __shared__ ulonglong2 ex[2][8][32];

    const int tid   = threadIdx.x;
    const int g     = blockIdx.x * 256 + tid;
    const int lane  = tid & 31;
    const int warp  = tid >> 5;
    const int s     = g & 7;
    const int layer = s >> 1;
    const int half  = s & 1;
    const int b     = g >> 3;
    const bool l0   = (layer == 0);

    // Exchange slot indices within the warp's 8-lane batch group.
    const int grpbase = lane & ~7;
    const int prev0   = grpbase | (((layer + 3) & 3) << 1);
    const int prev1   = prev0 + 1;
    const int partner = lane ^ 1;

    ulonglong2* buf0 = ex[0][warp];
    ulonglong2* buf1 = ex[1][warp];

    // Weights in k-pair form.
    //   wiT[j][m]: input-weight pair for own output j vs input pair m.
    //   whT[j][m]: hidden-weight pair; multiplier slots [own0,own1,oth0,oth1],
    //              so half==1 loads its k-pairs permuted by m^2.
    u64 wiT[4][4], whT[4][4], biasp[4];
    #pragma unroll
    for (int j = 0; j < 4; ++j) {
        const int ju = half * 4 + j;   // global output unit
        biasp[j] = pack2(b_ih[layer * 8 + ju] + b_hh[layer * 8 + ju], 0.0f);
        #pragma unroll
        for (int m = 0; m < 4; ++m) {
            float w0, w1;
            if (l0) {
                w0 = (m == 0) ? W_ih0[ju] : 0.0f;
                w1 = 0.0f;
            } else {
                w0 = W_ih_rest[((layer - 1) * 8 + ju) * 8 + 2 * m];
                w1 = W_ih_rest[((layer - 1) * 8 + ju) * 8 + 2 * m + 1];
            }
            wiT[j][m] = pack2(w0, w1);
            const int kp = half ? (m ^ 2) : m;   // per-half column permutation
            whT[j][m] = pack2(W_hh[(layer * 8 + ju) * 8 + 2 * kp],
                              W_hh[(layer * 8 + ju) * 8 + 2 * kp + 1]);
        }
    }
    const u64 zero64 = pack2(0.0f, 0.0f);

    // Own hidden state: units [half*4 .. half*4+3] as two f32x2 pairs.
    u64 hp0, hp1;
    {
        const float* hsrc = h0 + ((size_t)(layer * B + b)) * 8 + half * 4;
        hp0 = pack2(hsrc[0], hsrc[1]);
        hp1 = pack2(hsrc[2], hsrc[3]);
    }

    const int NITER = T + 3;           // layer 3 finishes t=T-1 at i=T+2

    // 4-deep x prefetch ring (layer-0 threads only).
    float xr[4];
    #pragma unroll
    for (int p = 0; p < 4; ++p)
        xr[p] = (l0 && p < T) ? x[p * B + b] : 0.0f;
    const float* xp = x + (size_t)4 * B + b;

    // Seed exchange buffer 0 with h0 for iteration 0's reads.
    buf0[lane] = make_ulonglong2(hp0, hp1);
    __syncwarp();

    // Phase 1: head, 4 guarded iterations (t<0 lanes keep h0).
    ONE_STEP(0, 0, true, true, buf0, buf1);
    ONE_STEP(1, 1, true, true, buf1, buf0);
    ONE_STEP(2, 2, true, true, buf0, buf1);
    ONE_STEP(3, 3, true, true, buf1, buf0);

    // Phase 2: main loop, no guards (prefetch index i+4 <= T-1 guaranteed).
    const int main_end = (T - 4) & ~3;   // multiple of 4
    for (int io = 4; io < main_end; io += 4) {
        ONE_STEP(io + 0, 0, false, false, buf0, buf1);
        ONE_STEP(io + 1, 1, false, false, buf1, buf0);
        ONE_STEP(io + 2, 2, false, false, buf0, buf1);
        ONE_STEP(io + 3, 3, false, false, buf1, buf0);
    }

    // Phase 3: epilogue, guarded prefetch only. Post-T updates of layers 0-2
    // are unused and finite; layer 3's last update is exactly t=T-1.
    for (int i = main_end; i < NITER; ++i) {
        ulonglong2* rd = (i & 1) ? buf1 : buf0;
        ulonglong2* wr = (i & 1) ? buf0 : buf1;
        ONE_STEP(i, i & 3, false, true, rd, wr);
    }

    // Readout: layer-3 threads hold h(t=T-1); combine halves via one shuffle.
    float p0, p1, p2, p3;
    unpack2(hp0, p0, p1);
    unpack2(hp1, p2, p3);
    float part = p0 * W_out[half * 4 + 0] + p1 * W_out[half * 4 + 1]
               + p2 * W_out[half * 4 + 2] + p3 * W_out[half * 4 + 3];
    const float other = __shfl_sync(0xffffffffu, part, partner);
    if (layer == 3 && half == 0)
        out[b] = part + other + b_out[0];
}

extern "C" void kernel_launch(void* const* d_in, const int* in_sizes, int n_in,
                              void* d_out, int out_size) {
    const float* x         = (const float*)d_in[0];
    const float* h0        = (const float*)d_in[1];
    const float* W_ih0     = (const float*)d_in[2];
    const float* W_ih_rest = (const float*)d_in[3];
    const float* W_hh      = (const float*)d_in[4];
    const float* b_ih      = (const float*)d_in[5];
    const float* b_hh      = (const float*)d_in[6];
    const float* W_out     = (const float*)d_in[7];
    const float* b_out     = (const float*)d_in[8];

    const int B = in_sizes[1] / 32;   // h0: [4, B, 8]
    const int T = in_sizes[0] / B;    // x:  [T, B, 1]

    const int threads = 8 * B;        // 8 threads per batch element
    const int block   = 256;          // 8 warps -> 2 warps per SMSP, uniform
    const int grid    = (threads + block - 1) / block;

    rnn8s_kernel<<<grid, block>>>(x, h0, W_ih0, W_ih_rest, W_hh, b_ih, b_hh,
                                  W_out, b_out, (float*)d_out, T, B);
}

// round 5
// speedup vs baseline: 1.1549x; 1.1131x over previous
#include <cuda_runtime.h>

typedef unsigned long long u64;

__device__ __forceinline__ u64 pack2(float lo, float hi) {
    u64 r;
    asm("mov.b64 %0, {%1, %2};" : "=l"(r) : "r"(__float_as_uint(lo)), "r"(__float_as_uint(hi)));
    return r;
}
__device__ __forceinline__ void unpack2(u64 v, float& lo, float& hi) {
    unsigned int a, b;
    asm("mov.b64 {%0, %1}, %2;" : "=r"(a), "=r"(b) : "l"(v));
    lo = __uint_as_float(a);
    hi = __uint_as_float(b);
}
// Packed fp32x2 FMA (Blackwell FFMA2).
__device__ __forceinline__ u64 ffma2(u64 a, u64 b, u64 c) {
    u64 d;
    asm("fma.rn.f32x2 %0, %1, %2, %3;" : "=l"(d) : "l"(a), "l"(b), "l"(c));
    return d;
}
__device__ __forceinline__ float tanh_fast(float x) {
    float y;
    asm("tanh.approx.f32 %0, %1;" : "=f"(y) : "f"(x));
    return y;
}
// 64-bit shuffle via two 32-bit SHFL.IDX (halves; movs elide when aligned).
__device__ __forceinline__ u64 shfl64_up1(u64 v) {
    unsigned int a, b;
    asm("mov.b64 {%0, %1}, %2;" : "=r"(a), "=r"(b) : "l"(v));
    a = __shfl_up_sync(0xffffffffu, a, 1);
    b = __shfl_up_sync(0xffffffffu, b, 1);
    u64 r;
    asm("mov.b64 %0, {%1, %2};" : "=l"(r) : "r"(a), "r"(b));
    return r;
}

// Systolic 4-layer tanh RNN, 4 threads per batch element (lane role = layer).
// Layer l at iteration i computes timestep t = i - l, consuming layer (l-1)'s
// previous-iteration output via __shfl_up(1) of the PACKED h pairs.
//
// Pure k-pair accumulation: each output j has ONE 8-deep FFMA2 chain whose
// multipliers are [hp0..hp3 (own h pairs), in0..in3 (prev-layer pairs)] — all
// naturally packed registers, zero broadcast packs. acc[j] is an f32x2 of two
// partial sums, horizontally combined (1 FADD) before tanh. Bias rides in the
// lo half of the chain start.
//
// Layer 0: multiplier slot 4 becomes (x,x); its weight pair is (W_ih0[j], 0)
// so the hi half contributes 0, and slots 5..7 have zero weights making the
// wrapped-lane garbage inert.
//
// ONE_STEP: HEADG = guard h update for t<0; PFG = guard x prefetch vs T.
#define ONE_STEP(IVAL, U, HEADG, PFG)                                           \
    do {                                                                        \
        const int i_ = (IVAL);                                                  \
        /* prev-layer packed pairs (8 SHFL32 total) */                          \
        const u64 in0 = shfl64_up1(hp0);                                        \
        const u64 in1 = shfl64_up1(hp1);                                        \
        const u64 in2 = shfl64_up1(hp2);                                        \
        const u64 in3 = shfl64_up1(hp3);                                        \
        const u64 d4 = l0 ? pack2(xr[U], xr[U]) : in0;                          \
        u64 a0 = bias[0], a1 = bias[1], a2 = bias[2], a3 = bias[3];             \
        u64 a4 = bias[4], a5 = bias[5], a6 = bias[6], a7 = bias[7];             \
        /* m = 0..3: own-h pairs (independent of shfl, fills its latency) */    \
        a0 = ffma2(hp0, w[0][0], a0); a1 = ffma2(hp0, w[1][0], a1);             \
        a2 = ffma2(hp0, w[2][0], a2); a3 = ffma2(hp0, w[3][0], a3);             \
        a4 = ffma2(hp0, w[4][0], a4); a5 = ffma2(hp0, w[5][0], a5);             \
        a6 = ffma2(hp0, w[6][0], a6); a7 = ffma2(hp0, w[7][0], a7);             \
        a0 = ffma2(hp1, w[0][1], a0); a1 = ffma2(hp1, w[1][1], a1);             \
        a2 = ffma2(hp1, w[2][1], a2); a3 = ffma2(hp1, w[3][1], a3);             \
        a4 = ffma2(hp1, w[4][1], a4); a5 = ffma2(hp1, w[5][1], a5);             \
        a6 = ffma2(hp1, w[6][1], a6); a7 = ffma2(hp1, w[7][1], a7);             \
        a0 = ffma2(hp2, w[0][2], a0); a1 = ffma2(hp2, w[1][2], a1);             \
        a2 = ffma2(hp2, w[2][2], a2); a3 = ffma2(hp2, w[3][2], a3);             \
        a4 = ffma2(hp2, w[4][2], a4); a5 = ffma2(hp2, w[5][2], a5);             \
        a6 = ffma2(hp2, w[6][2], a6); a7 = ffma2(hp2, w[7][2], a7);             \
        a0 = ffma2(hp3, w[0][3], a0); a1 = ffma2(hp3, w[1][3], a1);             \
        a2 = ffma2(hp3, w[2][3], a2); a3 = ffma2(hp3, w[3][3], a3);             \
        a4 = ffma2(hp3, w[4][3], a4); a5 = ffma2(hp3, w[5][3], a5);             \
        a6 = ffma2(hp3, w[6][3], a6); a7 = ffma2(hp3, w[7][3], a7);             \
        /* m = 4..7: prev-layer pairs */                                        \
        a0 = ffma2(d4,  w[0][4], a0); a1 = ffma2(d4,  w[1][4], a1);             \
        a2 = ffma2(d4,  w[2][4], a2); a3 = ffma2(d4,  w[3][4], a3);             \
        a4 = ffma2(d4,  w[4][4], a4); a5 = ffma2(d4,  w[5][4], a5);             \
        a6 = ffma2(d4,  w[6][4], a6); a7 = ffma2(d4,  w[7][4], a7);             \
        a0 = ffma2(in1, w[0][5], a0); a1 = ffma2(in1, w[1][5], a1);             \
        a2 = ffma2(in1, w[2][5], a2); a3 = ffma2(in1, w[3][5], a3);             \
        a4 = ffma2(in1, w[4][5], a4); a5 = ffma2(in1, w[5][5], a5);             \
        a6 = ffma2(in1, w[6][5], a6); a7 = ffma2(in1, w[7][5], a7);             \
        a0 = ffma2(in2, w[0][6], a0); a1 = ffma2(in2, w[1][6], a1);             \
        a2 = ffma2(in2, w[2][6], a2); a3 = ffma2(in2, w[3][6], a3);             \
        a4 = ffma2(in2, w[4][6], a4); a5 = ffma2(in2, w[5][6], a5);             \
        a6 = ffma2(in2, w[6][6], a6); a7 = ffma2(in2, w[7][6], a7);             \
        a0 = ffma2(in3, w[0][7], a0); a1 = ffma2(in3, w[1][7], a1);             \
        a2 = ffma2(in3, w[2][7], a2); a3 = ffma2(in3, w[3][7], a3);             \
        a4 = ffma2(in3, w[4][7], a4); a5 = ffma2(in3, w[5][7], a5);             \
        a6 = ffma2(in3, w[6][7], a6); a7 = ffma2(in3, w[7][7], a7);             \
        /* horizontal combine + activation */                                   \
        float lo_, hi_;                                                         \
        unpack2(a0, lo_, hi_); const float n0 = tanh_fast(lo_ + hi_);           \
        unpack2(a1, lo_, hi_); const float n1 = tanh_fast(lo_ + hi_);           \
        unpack2(a2, lo_, hi_); const float n2 = tanh_fast(lo_ + hi_);           \
        unpack2(a3, lo_, hi_); const float n3 = tanh_fast(lo_ + hi_);           \
        unpack2(a4, lo_, hi_); const float n4 = tanh_fast(lo_ + hi_);           \
        unpack2(a5, lo_, hi_); const float n5 = tanh_fast(lo_ + hi_);           \
        unpack2(a6, lo_, hi_); const float n6 = tanh_fast(lo_ + hi_);           \
        unpack2(a7, lo_, hi_); const float n7 = tanh_fast(lo_ + hi_);           \
        if (HEADG) {                                                            \
            if ((i_ - layer) >= 0) {                                            \
                hp0 = pack2(n0, n1); hp1 = pack2(n2, n3);                       \
                hp2 = pack2(n4, n5); hp3 = pack2(n6, n7);                       \
            }                                                                   \
        } else {                                                                \
            hp0 = pack2(n0, n1); hp1 = pack2(n2, n3);                           \
            hp2 = pack2(n4, n5); hp3 = pack2(n6, n7);                           \
        }                                                                       \
        if (PFG) xr[U] = (l0 && (i_ + 4) < T) ? __ldg(xp) : 0.0f;               \
        else     xr[U] = l0 ? __ldg(xp) : 0.0f;                                 \
        xp += B;                                                                \
    } while (0)

__global__ void __launch_bounds__(128, 1) rnn4k_kernel(
    const float* __restrict__ x,        // [T, B]
    const float* __restrict__ h0,       // [4, B, 8]
    const float* __restrict__ W_ih0,    // [8, 1]
    const float* __restrict__ W_ih_rest,// [3, 8, 8]
    const float* __restrict__ W_hh,     // [4, 8, 8]
    const float* __restrict__ b_ih,     // [4, 8]
    const float* __restrict__ b_hh,     // [4, 8]
    const float* __restrict__ W_out,    // [1, 8]
    const float* __restrict__ b_out,    // [1]
    float* __restrict__ out,            // [B]
    int T, int B)
{
    const int g     = blockIdx.x * blockDim.x + threadIdx.x;
    const int layer = g & 3;
    const int b     = g >> 2;
    if (b >= B) return;
    const bool l0 = (layer == 0);

    // Weight pairs per output j, multiplier slot m:
    //   m=0..3 -> W_hh[j][2m], W_hh[j][2m+1]  (own h pairs)
    //   m=4..7 -> W_ih[j][2(m-4)], W_ih[j][2(m-4)+1]  (prev-layer pairs)
    // Layer 0: m=4 -> (W_ih0[j], 0); m=5..7 -> (0,0).
    u64 w[8][8], bias[8];
    #pragma unroll
    for (int j = 0; j < 8; ++j) {
        bias[j] = pack2(b_ih[layer * 8 + j] + b_hh[layer * 8 + j], 0.0f);
        #pragma unroll
        for (int m = 0; m < 4; ++m)
            w[j][m] = pack2(W_hh[(layer * 8 + j) * 8 + 2 * m],
                            W_hh[(layer * 8 + j) * 8 + 2 * m + 1]);
        #pragma unroll
        for (int m = 4; m < 8; ++m) {
            float w0, w1;
            if (l0) {
                w0 = (m == 4) ? W_ih0[j] : 0.0f;
                w1 = 0.0f;
            } else {
                w0 = W_ih_rest[((layer - 1) * 8 + j) * 8 + 2 * (m - 4)];
                w1 = W_ih_rest[((layer - 1) * 8 + j) * 8 + 2 * (m - 4) + 1];
            }
            w[j][m] = pack2(w0, w1);
        }
    }

    // Own hidden state as four packed pairs.
    u64 hp0, hp1, hp2, hp3;
    {
        const float* hsrc = h0 + ((size_t)(layer * B + b)) * 8;
        hp0 = pack2(hsrc[0], hsrc[1]);
        hp1 = pack2(hsrc[2], hsrc[3]);
        hp2 = pack2(hsrc[4], hsrc[5]);
        hp3 = pack2(hsrc[6], hsrc[7]);
    }

    const int NITER = T + 3;           // layer 3 finishes t=T-1 at i=T+2

    // 4-deep x prefetch ring (layer-0 lanes only).
    float xr[4];
    #pragma unroll
    for (int p = 0; p < 4; ++p)
        xr[p] = (l0 && p < T) ? x[p * B + b] : 0.0f;
    const float* xp = x + (size_t)4 * B + b;

    // Phase 1: head, 4 guarded iterations (t<0 lanes keep h0).
    ONE_STEP(0, 0, true, true);
    ONE_STEP(1, 1, true, true);
    ONE_STEP(2, 2, true, true);
    ONE_STEP(3, 3, true, true);

    // Phase 2: main loop, no guards (prefetch index i+4 <= T-1 guaranteed).
    const int main_end = (T - 4) & ~3;   // multiple of 4
    for (int io = 4; io < main_end; io += 4) {
        ONE_STEP(io + 0, 0, false, false);
        ONE_STEP(io + 1, 1, false, false);
        ONE_STEP(io + 2, 2, false, false);
        ONE_STEP(io + 3, 3, false, false);
    }

    // Phase 3: epilogue, guarded prefetch only. Post-T updates of layers 0-2
    // are unused and finite; layer 3's last update is exactly t=T-1.
    for (int i = main_end; i < NITER; ++i)
        ONE_STEP(i, i & 3, false, true);

    // Readout: lanes holding layer 3 have h(t = T-1).
    if (layer == 3) {
        float p0, p1, p2, p3, p4, p5, p6, p7;
        unpack2(hp0, p0, p1);
        unpack2(hp1, p2, p3);
        unpack2(hp2, p4, p5);
        unpack2(hp3, p6, p7);
        float acc = b_out[0];
        acc = fmaf(p0, W_out[0], acc);
        acc = fmaf(p1, W_out[1], acc);
        acc = fmaf(p2, W_out[2], acc);
        acc = fmaf(p3, W_out[3], acc);
        acc = fmaf(p4, W_out[4], acc);
        acc = fmaf(p5, W_out[5], acc);
        acc = fmaf(p6, W_out[6], acc);
        acc = fmaf(p7, W_out[7], acc);
        out[b] = acc;
    }
}

extern "C" void kernel_launch(void* const* d_in, const int* in_sizes, int n_in,
                              void* d_out, int out_size) {
    const float* x         = (const float*)d_in[0];
    const float* h0        = (const float*)d_in[1];
    const float* W_ih0     = (const float*)d_in[2];
    const float* W_ih_rest = (const float*)d_in[3];
    const float* W_hh      = (const float*)d_in[4];
    const float* b_ih      = (const float*)d_in[5];
    const float* b_hh      = (const float*)d_in[6];
    const float* W_out     = (const float*)d_in[7];
    const float* b_out     = (const float*)d_in[8];

    const int B = in_sizes[1] / 32;   // h0: [4, B, 8]
    const int T = in_sizes[0] / B;    // x:  [T, B, 1]

    const int threads = 4 * B;
    const int block   = 128;
    const int grid    = (threads + block - 1) / block;

    rnn4k_kernel<<<grid, block>>>(x, h0, W_ih0, W_ih_rest, W_hh, b_ih, b_hh,
                                  W_out, b_out, (float*)d_out, T, B);
}